// round 1
// baseline (speedup 1.0000x reference)
#include <cuda_runtime.h>
#include <cstdint>

using ull = unsigned long long;

// ---------- packed f32x2 helpers (Blackwell sm_100a) ----------
__device__ __forceinline__ ull f2pack(float a, float b) {
    ull r; asm("mov.b64 %0, {%1, %2};" : "=l"(r) : "f"(a), "f"(b)); return r;
}
__device__ __forceinline__ void f2unpack(ull p, float& a, float& b) {
    asm("mov.b64 {%0, %1}, %2;" : "=f"(a), "=f"(b) : "l"(p));
}
__device__ __forceinline__ ull f2fma(ull a, ull b, ull c) {
    ull d; asm("fma.rn.f32x2 %0, %1, %2, %3;" : "=l"(d) : "l"(a), "l"(b), "l"(c)); return d;
}
__device__ __forceinline__ ull f2add(ull a, ull b) {
    ull d; asm("add.rn.f32x2 %0, %1, %2;" : "=l"(d) : "l"(a), "l"(b)); return d;
}
__device__ __forceinline__ ull f2mul(ull a, ull b) {
    ull d; asm("mul.rn.f32x2 %0, %1, %2;" : "=l"(d) : "l"(a), "l"(b)); return d;
}
__device__ __forceinline__ ull f2relu(ull p) {
    float a, b; f2unpack(p, a, b);
    a = fmaxf(a, 0.0f); b = fmaxf(b, 0.0f);
    return f2pack(a, b);
}
__device__ __forceinline__ ull f2splat(float x) { return f2pack(x, x); }
__device__ __forceinline__ float sigm(float x) { return 1.0f / (1.0f + __expf(-x)); }

// Layout constants
#define V_GSTRIDE 169   // per-group stride in s_v (ull units), padded to de-bank
#define V_JSTRIDE 21    // per-phase stride

__global__ __launch_bounds__(128, 4)
void frap_kernel(const float* __restrict__ states,
                 const int*   __restrict__ comp_mask,
                 const int*   __restrict__ phase_pairs,
                 const float* __restrict__ p_w,
                 const float* __restrict__ d_w,  const float* __restrict__ d_b,
                 const float* __restrict__ le_w, const float* __restrict__ le_b,
                 const float* __restrict__ lc_w, const float* __restrict__ lc_b,
                 const float* __restrict__ rel_w,
                 const float* __restrict__ rc_w, const float* __restrict__ rc_b,
                 const float* __restrict__ h_w,  const float* __restrict__ h_b,
                 const float* __restrict__ bm_w, const float* __restrict__ bm_b,
                 float* __restrict__ out, int B)
{
    // All weights pre-splatted to (w,w) packed f32x2 so LDS64 feeds FFMA2 directly.
    __shared__ ull  s_lcA[20][16];     // lc_w[:, 0:16]
    __shared__ ull  s_lcB[20][16];     // lc_w[:, 16:32]
    __shared__ ull  s_hw[20][20];
    __shared__ ull  s_rel[56][20];     // relu(relu(rel_w[comp_mask]) @ rc_w^T + rc_b)
    __shared__ ull  s_leD[4][16];      // le_w[4:8, :]
    __shared__ ull  s_lcb[20], s_hb[20], s_bmw[20], s_dw[4], s_db[4];
    __shared__ float s_base[2][16];    // le_b + sigmoid(p_w[e]) @ le_w[0:4, :]  (NOT splatted)
    __shared__ int   s_pp[16];
    __shared__ float s_bmb;
    __shared__ ull  s_v[16 * V_GSTRIDE];  // per-group v[8][20] exchange (padded)

    const int tid = threadIdx.x;

    // ---------------- block-local precompute (cheap, batch-independent) ----------------
    for (int idx = tid; idx < 320; idx += 128) {
        int o = idx >> 4, c = idx & 15;
        s_lcA[o][c] = f2splat(lc_w[o * 32 + c]);
        s_lcB[o][c] = f2splat(lc_w[o * 32 + 16 + c]);
    }
    for (int idx = tid; idx < 400; idx += 128) {
        int o = idx / 20, c = idx % 20;
        s_hw[o][c] = f2splat(h_w[o * 20 + c]);
    }
    for (int idx = tid; idx < 1120; idx += 128) {
        int pq = idx / 20, o = idx % 20;
        int e = comp_mask[pq];          // [8][7] row-major, in {0,1}
        float acc = rc_b[o];
        #pragma unroll
        for (int c4 = 0; c4 < 4; c4++) {
            float t = fmaxf(rel_w[e * 4 + c4], 0.0f);
            acc += t * rc_w[o * 4 + c4];
        }
        s_rel[pq][o] = f2splat(fmaxf(acc, 0.0f));
    }
    for (int idx = tid; idx < 64; idx += 128) {
        int k = idx >> 4, c = idx & 15;
        s_leD[k][c] = f2splat(le_w[(4 + k) * 16 + c]);
    }
    if (tid < 32) {
        int e = tid >> 4, c = tid & 15;
        float a = le_b[c];
        #pragma unroll
        for (int k = 0; k < 4; k++) a += sigm(p_w[e * 4 + k]) * le_w[k * 16 + c];
        s_base[e][c] = a;
    }
    if (tid < 20) {
        s_lcb[tid] = f2splat(lc_b[tid]);
        s_hb[tid]  = f2splat(h_b[tid]);
        s_bmw[tid] = f2splat(bm_w[tid]);
    }
    if (tid < 4) { s_dw[tid] = f2splat(d_w[tid]); s_db[tid] = f2splat(d_b[tid]); }
    if (tid < 16) s_pp[tid] = phase_pairs[tid];
    if (tid == 0) s_bmb = bm_b[0];
    __syncthreads();

    // ---------------- per-thread: (batch pair bp) x (phase i) ----------------
    const int g = tid >> 3;        // group 0..15 (one batch-pair)
    const int i = tid & 7;         // output phase
    const long long bp = (long long)blockIdx.x * 16 + g;
    const long long b0 = 2 * bp, b1 = b0 + 1;
    const bool valid0 = (b0 < B), valid1 = (b1 < B);
    const float* st0 = states + (valid0 ? b0 : 0) * 13;
    const float* st1 = states + (valid1 ? b1 : 0) * 13;

    const int a0 = (int)st0[0], a1 = (int)st1[0];
    const int p00 = s_pp[a0 * 2], p01 = s_pp[a0 * 2 + 1];
    const int p10 = s_pp[a1 * 2], p11 = s_pp[a1 * 2 + 1];
    const int mA = s_pp[i * 2], mB = s_pp[i * 2 + 1];

    // pairs[i] = lane[mA] + lane[mB], both batch elems packed (x=b0, y=b1)
    ull pairs[16];
    #pragma unroll
    for (int c = 0; c < 16; c++) pairs[c] = 0ULL;

    #pragma unroll
    for (int t = 0; t < 2; t++) {
        const int m = (t == 0) ? mA : mB;
        const ull dm = f2pack(st0[1 + m], st1[1 + m]);
        ull de[4];
        #pragma unroll
        for (int k = 0; k < 4; k++) {
            float x, y; f2unpack(f2fma(dm, s_dw[k], s_db[k]), x, y);
            de[k] = f2pack(sigm(x), sigm(y));
        }
        const int e0 = (m == p00 || m == p01) ? 1 : 0;
        const int e1 = (m == p10 || m == p11) ? 1 : 0;
        #pragma unroll
        for (int c = 0; c < 16; c++) {
            ull acc = f2pack(s_base[e0][c], s_base[e1][c]);
            #pragma unroll
            for (int k = 0; k < 4; k++) acc = f2fma(de[k], s_leD[k][c], acc);
            pairs[c] = f2add(pairs[c], f2relu(acc));
        }
    }

    // u = lcA @ pairs + lc_b (kept in regs); v = lcB @ pairs (to shared for exchange)
    ull u[20];
    #pragma unroll
    for (int o = 0; o < 20; o++) {
        ull au = s_lcb[o];
        ull av = 0ULL;
        #pragma unroll
        for (int c = 0; c < 16; c++) {
            au = f2fma(s_lcA[o][c], pairs[c], au);
            av = f2fma(s_lcB[o][c], pairs[c], av);
        }
        u[o] = au;
        s_v[g * V_GSTRIDE + i * V_JSTRIDE + o] = av;
    }
    __syncthreads();

    // j-loop: rot = relu(u + v_j); comb = rot * rel; h = relu(h_w@comb + h_b); acc += bm_w·h
    ull acc = 0ULL;
    #pragma unroll 1
    for (int q = 0; q < 7; q++) {
        const int j = q + (q >= i ? 1 : 0);
        const ull* vj = &s_v[g * V_GSTRIDE + j * V_JSTRIDE];
        const ull* rl = &s_rel[i * 7 + q][0];
        ull comb[20];
        #pragma unroll
        for (int c = 0; c < 20; c++)
            comb[c] = f2mul(f2relu(f2add(u[c], vj[c])), rl[c]);
        #pragma unroll
        for (int o = 0; o < 20; o++) {
            ull h = s_hb[o];
            #pragma unroll
            for (int c = 0; c < 20; c++) h = f2fma(s_hw[o][c], comb[c], h);
            acc = f2fma(s_bmw[o], f2relu(h), acc);
        }
    }

    float ax, ay; f2unpack(acc, ax, ay);
    const float bias7 = 7.0f * s_bmb;
    if (valid0) out[b0 * 8 + i] = ax + bias7;
    if (valid1) out[b1 * 8 + i] = ay + bias7;
}

extern "C" void kernel_launch(void* const* d_in, const int* in_sizes, int n_in,
                              void* d_out, int out_size)
{
    const float* states      = (const float*)d_in[0];
    const int*   comp_mask   = (const int*)  d_in[1];
    const int*   phase_pairs = (const int*)  d_in[2];
    const float* p_w  = (const float*)d_in[3];
    const float* d_w  = (const float*)d_in[4];
    const float* d_b  = (const float*)d_in[5];
    const float* le_w = (const float*)d_in[6];
    const float* le_b = (const float*)d_in[7];
    const float* lc_w = (const float*)d_in[8];
    const float* lc_b = (const float*)d_in[9];
    const float* rel_w = (const float*)d_in[10];
    const float* rc_w  = (const float*)d_in[11];
    const float* rc_b  = (const float*)d_in[12];
    const float* h_w   = (const float*)d_in[13];
    const float* h_b   = (const float*)d_in[14];
    const float* bm_w  = (const float*)d_in[15];
    const float* bm_b  = (const float*)d_in[16];

    const int B = in_sizes[0] / 13;           // states is [B, 1 + 12]
    const int blocks = (B + 31) / 32;         // 16 batch-pairs (32 batch elems) per block

    frap_kernel<<<blocks, 128>>>(states, comp_mask, phase_pairs,
                                 p_w, d_w, d_b, le_w, le_b, lc_w, lc_b,
                                 rel_w, rc_w, rc_b, h_w, h_b, bm_w, bm_b,
                                 (float*)d_out, B);
}

// round 2
// speedup vs baseline: 1.1430x; 1.1430x over previous
#include <cuda_runtime.h>
#include <cstdint>

using ull = unsigned long long;

// ---------- packed f32x2 helpers (Blackwell sm_100a) ----------
__device__ __forceinline__ ull f2pack(float a, float b) {
    ull r; asm("mov.b64 %0, {%1, %2};" : "=l"(r) : "f"(a), "f"(b)); return r;
}
__device__ __forceinline__ void f2unpack(ull p, float& a, float& b) {
    asm("mov.b64 {%0, %1}, %2;" : "=f"(a), "=f"(b) : "l"(p));
}
__device__ __forceinline__ ull f2fma(ull a, ull b, ull c) {
    ull d; asm("fma.rn.f32x2 %0, %1, %2, %3;" : "=l"(d) : "l"(a), "l"(b), "l"(c)); return d;
}
__device__ __forceinline__ ull f2add(ull a, ull b) {
    ull d; asm("add.rn.f32x2 %0, %1, %2;" : "=l"(d) : "l"(a), "l"(b)); return d;
}
__device__ __forceinline__ ull f2mul(ull a, ull b) {
    ull d; asm("mul.rn.f32x2 %0, %1, %2;" : "=l"(d) : "l"(a), "l"(b)); return d;
}
__device__ __forceinline__ ull f2relu(ull p) {
    float a, b; f2unpack(p, a, b);
    a = fmaxf(a, 0.0f); b = fmaxf(b, 0.0f);
    return f2pack(a, b);
}
__device__ __forceinline__ ull f2splat(float x) { return f2pack(x, x); }
__device__ __forceinline__ float sigm(float x) { return 1.0f / (1.0f + __expf(-x)); }

// Layout constants
#define V_GSTRIDE 169   // per-group stride in s_v (ull units), padded to de-bank
#define V_JSTRIDE 21    // per-phase stride

// 2 blocks/SM max -> 256-register budget per thread: the ull working set
// (u[20]+comb[20]+pairs[16] etc.) must stay in registers, NOT local memory.
__global__ __launch_bounds__(128, 2)
void frap_kernel(const float* __restrict__ states,
                 const int*   __restrict__ comp_mask,
                 const int*   __restrict__ phase_pairs,
                 const float* __restrict__ p_w,
                 const float* __restrict__ d_w,  const float* __restrict__ d_b,
                 const float* __restrict__ le_w, const float* __restrict__ le_b,
                 const float* __restrict__ lc_w, const float* __restrict__ lc_b,
                 const float* __restrict__ rel_w,
                 const float* __restrict__ rc_w, const float* __restrict__ rc_b,
                 const float* __restrict__ h_w,  const float* __restrict__ h_b,
                 const float* __restrict__ bm_w, const float* __restrict__ bm_b,
                 float* __restrict__ out, int B)
{
    // All weights pre-splatted to (w,w) packed f32x2 so LDS feeds FFMA2 directly.
    __shared__ ull  s_lcA[20][16];     // lc_w[:, 0:16]
    __shared__ ull  s_lcB[20][16];     // lc_w[:, 16:32]
    __shared__ ull  s_hw[20][20];      // rows are 160B (16B aligned) -> LDS128 pairs
    __shared__ ull  s_rel[56][20];     // relu(relu(rel_w[comp_mask]) @ rc_w^T + rc_b)
    __shared__ ull  s_leD[4][16];      // le_w[4:8, :]
    __shared__ ull  s_lcb[20], s_hb[20], s_bmw[20], s_dw[4], s_db[4];
    __shared__ float s_base[2][16];    // le_b + sigmoid(p_w[e]) @ le_w[0:4, :]
    __shared__ int   s_pp[16];
    __shared__ float s_bmb;
    __shared__ ull  s_v[16 * V_GSTRIDE];  // per-group v[8][20] exchange (padded)

    const int tid = threadIdx.x;

    // ---------------- block-local precompute (cheap, batch-independent) ----------------
    for (int idx = tid; idx < 320; idx += 128) {
        int o = idx >> 4, c = idx & 15;
        s_lcA[o][c] = f2splat(lc_w[o * 32 + c]);
        s_lcB[o][c] = f2splat(lc_w[o * 32 + 16 + c]);
    }
    for (int idx = tid; idx < 400; idx += 128) {
        int o = idx / 20, c = idx % 20;
        s_hw[o][c] = f2splat(h_w[o * 20 + c]);
    }
    for (int idx = tid; idx < 1120; idx += 128) {
        int pq = idx / 20, o = idx % 20;
        int e = comp_mask[pq];          // [8][7] row-major, in {0,1}
        float acc = rc_b[o];
        #pragma unroll
        for (int c4 = 0; c4 < 4; c4++) {
            float t = fmaxf(rel_w[e * 4 + c4], 0.0f);
            acc += t * rc_w[o * 4 + c4];
        }
        s_rel[pq][o] = f2splat(fmaxf(acc, 0.0f));
    }
    for (int idx = tid; idx < 64; idx += 128) {
        int k = idx >> 4, c = idx & 15;
        s_leD[k][c] = f2splat(le_w[(4 + k) * 16 + c]);
    }
    if (tid < 32) {
        int e = tid >> 4, c = tid & 15;
        float a = le_b[c];
        #pragma unroll
        for (int k = 0; k < 4; k++) a += sigm(p_w[e * 4 + k]) * le_w[k * 16 + c];
        s_base[e][c] = a;
    }
    if (tid < 20) {
        s_lcb[tid] = f2splat(lc_b[tid]);
        s_hb[tid]  = f2splat(h_b[tid]);
        s_bmw[tid] = f2splat(bm_w[tid]);
    }
    if (tid < 4) { s_dw[tid] = f2splat(d_w[tid]); s_db[tid] = f2splat(d_b[tid]); }
    if (tid < 16) s_pp[tid] = phase_pairs[tid];
    if (tid == 0) s_bmb = bm_b[0];
    __syncthreads();

    // ---------------- per-thread: (batch pair bp) x (phase i) ----------------
    const int g = tid >> 3;        // group 0..15 (one batch-pair)
    const int i = tid & 7;         // output phase
    const long long bp = (long long)blockIdx.x * 16 + g;
    const long long b0 = 2 * bp, b1 = b0 + 1;
    const bool valid0 = (b0 < B), valid1 = (b1 < B);
    const float* st0 = states + (valid0 ? b0 : 0) * 13;
    const float* st1 = states + (valid1 ? b1 : 0) * 13;

    const int a0 = (int)st0[0], a1 = (int)st1[0];
    const int p00 = s_pp[a0 * 2], p01 = s_pp[a0 * 2 + 1];
    const int p10 = s_pp[a1 * 2], p11 = s_pp[a1 * 2 + 1];
    const int mA = s_pp[i * 2], mB = s_pp[i * 2 + 1];

    // pairs[i] = lane[mA] + lane[mB], both batch elems packed (x=b0, y=b1)
    ull pairs[16];
    #pragma unroll
    for (int c = 0; c < 16; c++) pairs[c] = 0ULL;

    #pragma unroll
    for (int t = 0; t < 2; t++) {
        const int m = (t == 0) ? mA : mB;
        const ull dm = f2pack(st0[1 + m], st1[1 + m]);
        ull de[4];
        #pragma unroll
        for (int k = 0; k < 4; k++) {
            float x, y; f2unpack(f2fma(dm, s_dw[k], s_db[k]), x, y);
            de[k] = f2pack(sigm(x), sigm(y));
        }
        const int e0 = (m == p00 || m == p01) ? 1 : 0;
        const int e1 = (m == p10 || m == p11) ? 1 : 0;
        #pragma unroll
        for (int c = 0; c < 16; c++) {
            ull acc = f2pack(s_base[e0][c], s_base[e1][c]);
            #pragma unroll
            for (int k = 0; k < 4; k++) acc = f2fma(de[k], s_leD[k][c], acc);
            pairs[c] = f2add(pairs[c], f2relu(acc));
        }
    }

    // u = lcA @ pairs + lc_b (kept in regs); v = lcB @ pairs (to shared for exchange)
    ull u[20];
    #pragma unroll
    for (int o = 0; o < 20; o++) {
        ull au = s_lcb[o];
        ull av = 0ULL;
        #pragma unroll
        for (int c = 0; c < 16; c++) {
            au = f2fma(s_lcA[o][c], pairs[c], au);
            av = f2fma(s_lcB[o][c], pairs[c], av);
        }
        u[o] = au;
        s_v[g * V_GSTRIDE + i * V_JSTRIDE + o] = av;
    }
    __syncthreads();

    // j-loop: rot = relu(u + v_j); comb = rot * rel; h = relu(h_w@comb + h_b); acc += bm_w*h
    ull acc = 0ULL;
    #pragma unroll 1
    for (int q = 0; q < 7; q++) {
        const int j = q + (q >= i ? 1 : 0);
        const ull* vj = &s_v[g * V_GSTRIDE + j * V_JSTRIDE];
        const ull* rl = &s_rel[i * 7 + q][0];
        ull comb[20];
        #pragma unroll
        for (int c = 0; c < 20; c++)
            comb[c] = f2mul(f2relu(f2add(u[c], vj[c])), rl[c]);
        #pragma unroll
        for (int o = 0; o < 20; o++) {
            ull h = s_hb[o];
            // unrolled x2 over c: adjacent LDS64 of s_hw merge into LDS128
            #pragma unroll
            for (int c = 0; c < 20; c += 2) {
                h = f2fma(s_hw[o][c],     comb[c],     h);
                h = f2fma(s_hw[o][c + 1], comb[c + 1], h);
            }
            acc = f2fma(s_bmw[o], f2relu(h), acc);
        }
    }

    float ax, ay; f2unpack(acc, ax, ay);
    const float bias7 = 7.0f * s_bmb;
    if (valid0) out[b0 * 8 + i] = ax + bias7;
    if (valid1) out[b1 * 8 + i] = ay + bias7;
}

extern "C" void kernel_launch(void* const* d_in, const int* in_sizes, int n_in,
                              void* d_out, int out_size)
{
    const float* states      = (const float*)d_in[0];
    const int*   comp_mask   = (const int*)  d_in[1];
    const int*   phase_pairs = (const int*)  d_in[2];
    const float* p_w  = (const float*)d_in[3];
    const float* d_w  = (const float*)d_in[4];
    const float* d_b  = (const float*)d_in[5];
    const float* le_w = (const float*)d_in[6];
    const float* le_b = (const float*)d_in[7];
    const float* lc_w = (const float*)d_in[8];
    const float* lc_b = (const float*)d_in[9];
    const float* rel_w = (const float*)d_in[10];
    const float* rc_w  = (const float*)d_in[11];
    const float* rc_b  = (const float*)d_in[12];
    const float* h_w   = (const float*)d_in[13];
    const float* h_b   = (const float*)d_in[14];
    const float* bm_w  = (const float*)d_in[15];
    const float* bm_b  = (const float*)d_in[16];

    const int B = in_sizes[0] / 13;           // states is [B, 1 + 12]
    const int blocks = (B + 31) / 32;         // 16 batch-pairs (32 batch elems) per block

    frap_kernel<<<blocks, 128>>>(states, comp_mask, phase_pairs,
                                 p_w, d_w, d_b, le_w, le_b, lc_w, lc_b,
                                 rel_w, rc_w, rc_b, h_w, h_b, bm_w, bm_b,
                                 (float*)d_out, B);
}

// round 3
// speedup vs baseline: 2.5415x; 2.2236x over previous
#include <cuda_runtime.h>
#include <cstdint>

__device__ __forceinline__ float sigm(float x) { return 1.0f / (1.0f + __expf(-x)); }

#define V_GSTRIDE 169   // per-batch-elem stride in s_v (floats), keeps bank pattern conflict-free
#define V_JSTRIDE 21    // per-phase stride (21: conflict-free across warp)

// Scalar fp32: small live set (~70-100 regs), no 64-bit register-pair fragmentation,
// no spills. 3 blocks/SM -> ~168-reg budget gives ptxas slack for LDS batching.
__global__ __launch_bounds__(128, 3)
void frap_kernel(const float* __restrict__ states,
                 const int*   __restrict__ comp_mask,
                 const int*   __restrict__ phase_pairs,
                 const float* __restrict__ p_w,
                 const float* __restrict__ d_w,  const float* __restrict__ d_b,
                 const float* __restrict__ le_w, const float* __restrict__ le_b,
                 const float* __restrict__ lc_w, const float* __restrict__ lc_b,
                 const float* __restrict__ rel_w,
                 const float* __restrict__ rc_w, const float* __restrict__ rc_b,
                 const float* __restrict__ h_w,  const float* __restrict__ h_b,
                 const float* __restrict__ bm_w, const float* __restrict__ bm_b,
                 float* __restrict__ out, int B)
{
    __shared__ float s_lcA[20][16];         // lc_w[:, 0:16]
    __shared__ float s_lcB[20][16];         // lc_w[:, 16:32]
    __shared__ __align__(16) float s_hw[20][20];   // rows 80B, 16B-aligned -> float4 loads
    __shared__ float s_rel[56][20];         // relu(relu(rel_w[comp_mask]) @ rc_w^T + rc_b)
    __shared__ float s_leD[4][16];          // le_w[4:8, :]
    __shared__ float s_lcb[20], s_hb[20], s_bmw[20], s_dw[4], s_db[4];
    __shared__ float s_base[2][16];         // le_b + sigmoid(p_w[e]) @ le_w[0:4, :]
    __shared__ int   s_pp[16];
    __shared__ float s_bmb;
    __shared__ float s_v[16 * V_GSTRIDE];   // per-batch-elem v[8][20] exchange (padded)

    const int tid = threadIdx.x;

    // ---------------- block-local precompute (batch-independent, tiny) ----------------
    for (int idx = tid; idx < 320; idx += 128) {
        int o = idx >> 4, c = idx & 15;
        s_lcA[o][c] = lc_w[o * 32 + c];
        s_lcB[o][c] = lc_w[o * 32 + 16 + c];
    }
    for (int idx = tid; idx < 400; idx += 128) {
        int o = idx / 20, c = idx % 20;
        s_hw[o][c] = h_w[o * 20 + c];
    }
    for (int idx = tid; idx < 1120; idx += 128) {
        int pq = idx / 20, o = idx % 20;
        int e = comp_mask[pq];              // [8][7] row-major, in {0,1}
        float acc = rc_b[o];
        #pragma unroll
        for (int c4 = 0; c4 < 4; c4++)
            acc += fmaxf(rel_w[e * 4 + c4], 0.0f) * rc_w[o * 4 + c4];
        s_rel[pq][o] = fmaxf(acc, 0.0f);
    }
    for (int idx = tid; idx < 64; idx += 128) {
        int k = idx >> 4, c = idx & 15;
        s_leD[k][c] = le_w[(4 + k) * 16 + c];
    }
    if (tid < 32) {
        int e = tid >> 4, c = tid & 15;
        float a = le_b[c];
        #pragma unroll
        for (int k = 0; k < 4; k++) a += sigm(p_w[e * 4 + k]) * le_w[k * 16 + c];
        s_base[e][c] = a;
    }
    if (tid < 20) {
        s_lcb[tid] = lc_b[tid];
        s_hb[tid]  = h_b[tid];
        s_bmw[tid] = bm_w[tid];
    }
    if (tid < 4) { s_dw[tid] = d_w[tid]; s_db[tid] = d_b[tid]; }
    if (tid < 16) s_pp[tid] = phase_pairs[tid];
    if (tid == 0) s_bmb = bm_b[0];
    __syncthreads();

    // ---------------- per-thread: (batch elem b) x (output phase i) ----------------
    const int g = tid >> 3;                 // 0..15: batch elem within block
    const int i = tid & 7;                  // output phase
    const int b = blockIdx.x * 16 + g;
    const bool valid = (b < B);
    const float* st = states + (valid ? b : 0) * 13;

    const int a  = (int)st[0];
    const int pa0 = s_pp[a * 2], pa1 = s_pp[a * 2 + 1];
    const int mA  = s_pp[i * 2], mB  = s_pp[i * 2 + 1];

    // pairs[i] = lane[mA] + lane[mB]
    float pairs[16];
    #pragma unroll
    for (int c = 0; c < 16; c++) pairs[c] = 0.0f;

    #pragma unroll
    for (int t = 0; t < 2; t++) {
        const int m = (t == 0) ? mA : mB;
        const float dm = st[1 + m];
        float de[4];
        #pragma unroll
        for (int k = 0; k < 4; k++) de[k] = sigm(fmaf(dm, s_dw[k], s_db[k]));
        const int e = (m == pa0 || m == pa1) ? 1 : 0;
        #pragma unroll
        for (int c = 0; c < 16; c++) {
            float acc = s_base[e][c];
            #pragma unroll
            for (int k = 0; k < 4; k++) acc = fmaf(de[k], s_leD[k][c], acc);
            pairs[c] += fmaxf(acc, 0.0f);
        }
    }

    // u = lcA @ pairs + lc_b (regs); v = lcB @ pairs (to shared for cross-phase exchange)
    float u[20];
    #pragma unroll
    for (int o = 0; o < 20; o++) {
        float au = s_lcb[o];
        float av = 0.0f;
        #pragma unroll
        for (int c = 0; c < 16; c++) {
            au = fmaf(s_lcA[o][c], pairs[c], au);
            av = fmaf(s_lcB[o][c], pairs[c], av);
        }
        u[o] = au;
        s_v[g * V_GSTRIDE + i * V_JSTRIDE + o] = av;
    }
    __syncthreads();

    // j-loop: comb = relu(u + v_j) * rel[i][q]; h = relu(h_w@comb + h_b); acc += bm_w . h
    float acc = 0.0f;
    #pragma unroll 1
    for (int q = 0; q < 7; q++) {
        const int j = q + (q >= i ? 1 : 0);
        const float* vj = &s_v[g * V_GSTRIDE + j * V_JSTRIDE];
        const float* rl = &s_rel[i * 7 + q][0];
        float comb[20];
        #pragma unroll
        for (int c = 0; c < 20; c++)
            comb[c] = fmaxf(u[c] + vj[c], 0.0f) * rl[c];
        #pragma unroll
        for (int o = 0; o < 20; o++) {
            const float4* hw4 = reinterpret_cast<const float4*>(&s_hw[o][0]);
            float h = s_hb[o];
            #pragma unroll
            for (int c4 = 0; c4 < 5; c4++) {
                float4 w = hw4[c4];
                h = fmaf(w.x, comb[c4 * 4 + 0], h);
                h = fmaf(w.y, comb[c4 * 4 + 1], h);
                h = fmaf(w.z, comb[c4 * 4 + 2], h);
                h = fmaf(w.w, comb[c4 * 4 + 3], h);
            }
            acc = fmaf(s_bmw[o], fmaxf(h, 0.0f), acc);
        }
    }

    if (valid) out[b * 8 + i] = acc + 7.0f * s_bmb;   // coalesced: base*8 + tid
}

extern "C" void kernel_launch(void* const* d_in, const int* in_sizes, int n_in,
                              void* d_out, int out_size)
{
    const float* states      = (const float*)d_in[0];
    const int*   comp_mask   = (const int*)  d_in[1];
    const int*   phase_pairs = (const int*)  d_in[2];
    const float* p_w  = (const float*)d_in[3];
    const float* d_w  = (const float*)d_in[4];
    const float* d_b  = (const float*)d_in[5];
    const float* le_w = (const float*)d_in[6];
    const float* le_b = (const float*)d_in[7];
    const float* lc_w = (const float*)d_in[8];
    const float* lc_b = (const float*)d_in[9];
    const float* rel_w = (const float*)d_in[10];
    const float* rc_w  = (const float*)d_in[11];
    const float* rc_b  = (const float*)d_in[12];
    const float* h_w   = (const float*)d_in[13];
    const float* h_b   = (const float*)d_in[14];
    const float* bm_w  = (const float*)d_in[15];
    const float* bm_b  = (const float*)d_in[16];

    const int B = in_sizes[0] / 13;           // states is [B, 1 + 12]
    const int blocks = (B + 15) / 16;         // 16 batch elems x 8 phases per 128-thread block

    frap_kernel<<<blocks, 128>>>(states, comp_mask, phase_pairs,
                                 p_w, d_w, d_b, le_w, le_b, lc_w, lc_b,
                                 rel_w, rc_w, rc_b, h_w, h_b, bm_w, bm_b,
                                 (float*)d_out, B);
}